// round 3
// baseline (speedup 1.0000x reference)
#include <cuda_runtime.h>
#include <cuda_bf16.h>
#include <cstdint>

// Problem constants
#define BC      16            // B*C = 8*2
#define LL      2048          // sequence length
#define TSZ     17            // filter size
#define PAD     8             // TSZ/2

// xf stored TRANSPOSED: g_xf[bc][t][l]  (l contiguous)
__device__ float g_xf[BC * TSZ * LL];

// ---------------- f32x2 helpers (sm_103a packed fp32) ----------------
typedef double f32x2;

__device__ __forceinline__ f32x2 pack2(float lo, float hi) {
    f32x2 r;
    asm("mov.b64 %0, {%1, %2};" : "=d"(r) : "f"(lo), "f"(hi));
    return r;
}
__device__ __forceinline__ void ffma2(f32x2& d, f32x2 a, f32x2 b) {
    asm("fma.rn.f32x2 %0, %1, %2, %0;" : "+d"(d) : "d"(a), "d"(b));
}
__device__ __forceinline__ void unpack2(f32x2 v, float& lo, float& hi) {
    asm("mov.b64 {%0, %1}, %2;" : "=f"(lo), "=f"(hi) : "d"(v));
}

// ---------------- Kernel 0: xf[bc][t][l] = sum_s x[l+s-8] * filt[c][s][t] ----------------
__global__ void build_xf_kernel(const float* __restrict__ x,
                                const float* __restrict__ filt) {
    __shared__ float sf[TSZ * TSZ];
    int row = blockIdx.x * 256 + threadIdx.x;   // 0 .. BC*LL-1
    int bc = row >> 11;
    int l  = row & (LL - 1);
    int c  = bc & 1;

    for (int i = threadIdx.x; i < TSZ * TSZ; i += 256)
        sf[i] = filt[c * TSZ * TSZ + i];
    __syncthreads();

    float acc[TSZ];
#pragma unroll
    for (int t = 0; t < TSZ; t++) acc[t] = 0.0f;

    const float* xr = x + bc * LL;
#pragma unroll
    for (int s = 0; s < TSZ; s++) {
        int idx = l + s - PAD;
        float xv = (idx >= 0 && idx < LL) ? xr[idx] : 0.0f;
#pragma unroll
        for (int t = 0; t < TSZ; t++)
            acc[t] += xv * sf[s * TSZ + t];
    }

#pragma unroll
    for (int t = 0; t < TSZ; t++)
        g_xf[(bc * TSZ + t) * LL + l] = acc[t];   // transposed, coalesced
}

// ---------------- Kernel 1: main outer product ----------------
// out[bc][l][m] = sum_t xf[bc][t][l] * x[m+t-8]
// CTA tile: TL=64 (l) x TM=128 (m), 256 threads = 16(tx:m-groups) x 16(ty:l-groups)
// thread tile: 4 rows x 8 cols, acc paired over ROWS -> acc[2 rowpairs][8 m]
#define TL 64
#define TM 128

__global__ void __launch_bounds__(256, 2)
filter_main_kernel(const float* __restrict__ x, float* __restrict__ out) {
    __shared__ float sxf[TSZ][TL];        // xf tile, t-major
    __shared__ float sx[TM + 2 * PAD];    // x window for this m tile (144)

    const int bc = blockIdx.z;
    const int l0 = blockIdx.y * TL;
    const int m0 = blockIdx.x * TM;
    const int tid = threadIdx.x;
    const int tx = tid & 15;              // m group
    const int ty = tid >> 4;              // l group
    const int lg = ty * 4;                // local row base

    // ---- cooperative smem fill ----
    // sxf[t][j] = g_xf[bc][t][l0+j]
    for (int i = tid; i < TSZ * TL; i += 256) {
        int t = i >> 6;                   // /64
        int j = i & 63;
        sxf[t][j] = g_xf[(bc * TSZ + t) * LL + l0 + j];
    }
    // sx[i] = x[bc][m0 + i - 8] (zero-padded)
    if (tid < TM + 2 * PAD) {
        int idx = m0 + tid - PAD;
        sx[tid] = (idx >= 0 && idx < LL) ? x[bc * LL + idx] : 0.0f;
    }
    __syncthreads();

    // ---- broadcast pairs of x: bb[k] = (x_k, x_k), k = tx*8 .. tx*8+23 ----
    f32x2 bb[24];
#pragma unroll
    for (int k = 0; k < 24; k++) {
        float s = sx[tx * 8 + k];
        bb[k] = pack2(s, s);
    }

    // ---- accumulators: acc[rp][m], rp=0 -> rows (lg,lg+1), rp=1 -> (lg+2,lg+3) ----
    f32x2 acc0[8], acc1[8];
#pragma unroll
    for (int m = 0; m < 8; m++) { acc0[m] = 0.0; acc1[m] = 0.0; }

#pragma unroll
    for (int t = 0; t < TSZ; t++) {
        // one broadcast LDS.128: rows lg..lg+3 of tap t; register quad
        // natively provides the two f32x2 row-pairs (no pack MOVs needed)
        float4 av = *reinterpret_cast<const float4*>(&sxf[t][lg]);
        f32x2 a01 = pack2(av.x, av.y);
        f32x2 a23 = pack2(av.z, av.w);
#pragma unroll
        for (int m = 0; m < 8; m++) {
            ffma2(acc0[m], a01, bb[m + t]);
            ffma2(acc1[m], a23, bb[m + t]);
        }
    }

    // ---- store: 4 rows x 8 cols, 2x STG.128 per row ----
    const int mg = m0 + tx * 8;
    float r0[8], r1[8], r2[8], r3[8];
#pragma unroll
    for (int m = 0; m < 8; m++) {
        unpack2(acc0[m], r0[m], r1[m]);
        unpack2(acc1[m], r2[m], r3[m]);
    }
    float* base = out + ((size_t)(bc * LL + l0 + lg)) * LL + mg;
    float4* o0 = reinterpret_cast<float4*>(base);
    float4* o1 = reinterpret_cast<float4*>(base + LL);
    float4* o2 = reinterpret_cast<float4*>(base + 2 * LL);
    float4* o3 = reinterpret_cast<float4*>(base + 3 * LL);
    o0[0] = make_float4(r0[0], r0[1], r0[2], r0[3]);
    o0[1] = make_float4(r0[4], r0[5], r0[6], r0[7]);
    o1[0] = make_float4(r1[0], r1[1], r1[2], r1[3]);
    o1[1] = make_float4(r1[4], r1[5], r1[6], r1[7]);
    o2[0] = make_float4(r2[0], r2[1], r2[2], r2[3]);
    o2[1] = make_float4(r2[4], r2[5], r2[6], r2[7]);
    o3[0] = make_float4(r3[0], r3[1], r3[2], r3[3]);
    o3[1] = make_float4(r3[4], r3[5], r3[6], r3[7]);
}

extern "C" void kernel_launch(void* const* d_in, const int* in_sizes, int n_in,
                              void* d_out, int out_size) {
    const float* x    = (const float*)d_in[0];   // [8,2,2048]
    const float* filt = (const float*)d_in[1];   // [1,2,17,17]
    float* out = (float*)d_out;                  // [8,2,2048,2048]

    build_xf_kernel<<<(BC * LL) / 256, 256>>>(x, filt);

    dim3 grid(LL / TM, LL / TL, BC);
    filter_main_kernel<<<grid, 256>>>(x, out);
}